// round 3
// baseline (speedup 1.0000x reference)
#include <cuda_runtime.h>

// Problem constants (fixed by setup_inputs: N=50000, E=800000, D=100, 2 layers)
#define NMAX 50000
#define EMAX 800000
#define DD   100
#define C4   25      // D/4 float4 chunks per row
#define WPITCH 104   // padded pitch (floats) for transposed W rows (16B-aligned)

// ---- static device scratch (no runtime allocation allowed) ----
__device__ float g_bufA[NMAX * DD];        // GEMM output / SpMM input
__device__ float g_bufB[NMAX * DD];        // SpMM output (next layer input)
__device__ float g_Wt[2 * DD * WPITCH];    // k-major transposed weights
__device__ int   g_cnt[NMAX];              // per-row edge counts
__device__ int   g_rowptr[NMAX + 1];       // CSR row pointers
__device__ int   g_cursor[NMAX];           // scatter cursors
__device__ float g_deginv[NMAX];           // 1/(cnt+1)  (self loop included)
__device__ int   g_col[EMAX];              // CSR column (src) indices
__device__ int   g_bsums[64];
__device__ int   g_boffs[64];

// ---------------- preprocessing kernels ----------------

__global__ void zero_cnt_k(int N) {
    int i = blockIdx.x * blockDim.x + threadIdx.x;
    if (i < N) g_cnt[i] = 0;
}

__global__ void count_k(const int* __restrict__ dst, int E) {
    int i = blockIdx.x * blockDim.x + threadIdx.x;
    if (i < E) atomicAdd(&g_cnt[__ldg(&dst[i])], 1);
}

// transpose W (both layers) into k-major with padded pitch, coalesced reads
__global__ void transW_k(const float* __restrict__ W) {
    int i = blockIdx.x * blockDim.x + threadIdx.x;
    if (i < 2 * DD * DD) {
        int l = i / (DD * DD);
        int r = i - l * DD * DD;
        int j = r / DD;
        int k = r - j * DD;
        g_Wt[l * DD * WPITCH + k * WPITCH + j] = W[i];
    }
}

// per-1024-block exclusive scan of g_cnt -> g_rowptr (local), block sums -> g_bsums
__global__ void scanA_k(int N) {
    __shared__ int s[1024];
    int tid = threadIdx.x;
    int i = blockIdx.x * 1024 + tid;
    int v = (i < N) ? g_cnt[i] : 0;
    s[tid] = v;
    __syncthreads();
    #pragma unroll
    for (int off = 1; off < 1024; off <<= 1) {
        int t = 0;
        if (tid >= off) t = s[tid - off];
        __syncthreads();
        if (tid >= off) s[tid] += t;
        __syncthreads();
    }
    if (i < N) g_rowptr[i] = s[tid] - v;          // exclusive within block
    if (tid == 1023) g_bsums[blockIdx.x] = s[1023];
}

__global__ void scanB_k(int nb) {
    __shared__ int s[64];
    int tid = threadIdx.x;
    int v = (tid < nb) ? g_bsums[tid] : 0;
    s[tid] = v;
    __syncthreads();
    #pragma unroll
    for (int off = 1; off < 64; off <<= 1) {
        int t = 0;
        if (tid >= off) t = s[tid - off];
        __syncthreads();
        if (tid >= off) s[tid] += t;
        __syncthreads();
    }
    g_boffs[tid] = s[tid] - v;                    // exclusive block offsets
}

__global__ void scanC_k(int N, int E) {
    int i = blockIdx.x * blockDim.x + threadIdx.x;
    if (i < N) {
        int rp = g_rowptr[i] + g_boffs[i >> 10];
        g_rowptr[i] = rp;
        g_cursor[i] = rp;
        g_deginv[i] = 1.0f / (float)(g_cnt[i] + 1);   // +1 for self loop
    }
    if (i == 0) g_rowptr[N] = E;
}

__global__ void scatter_k(const int* __restrict__ src, const int* __restrict__ dst, int E) {
    int i = blockIdx.x * blockDim.x + threadIdx.x;
    if (i < E) {
        int d = __ldg(&dst[i]);
        int pos = atomicAdd(&g_cursor[d], 1);
        g_col[pos] = __ldg(&src[i]);
    }
}

// avg = features * (1/3)
__global__ void init_avg_k(const float* __restrict__ x, float* __restrict__ avg, int n4) {
    int i = blockIdx.x * blockDim.x + threadIdx.x;
    if (i < n4) {
        float4 v = ((const float4*)x)[i];
        const float c = 1.0f / 3.0f;
        v.x *= c; v.y *= c; v.z *= c; v.w *= c;
        ((float4*)avg)[i] = v;
    }
}

// ---------------- GEMM: out = x @ W[layer]^T  -> g_bufA ----------------
// Tile: 60 rows per CTA. 250 active threads: cg = tid%25 (4 output cols),
// rg = tid/25 (6 rows each). W (k-major, transposed) in SMEM: a warp's cg
// lanes read contiguous float4s -> conflict-free. x read via __ldg float4,
// broadcast across cg lanes (1-2 cache lines per LDG instruction).
__global__ void __launch_bounds__(256) gemm_k(const float* __restrict__ xin, int layer, int N) {
    __shared__ float Ws[DD * WPITCH];   // 41.6 KB
    const float* wt = g_Wt + layer * DD * WPITCH;
    for (int i = threadIdx.x; i < DD * WPITCH; i += 256) Ws[i] = wt[i];
    __syncthreads();

    int tid = threadIdx.x;
    if (tid >= 250) return;
    int cg = tid % 25;
    int rg = tid / 25;                 // 0..9
    int row0 = blockIdx.x * 60 + rg * 6;

    const float4* x4 = (const float4*)(xin ? xin : g_bufB);
    const float4* W4 = (const float4*)Ws;   // pitch: 26 float4 per k-row

    float4 acc[6];
    int ridx[6];
    #pragma unroll
    for (int i = 0; i < 6; ++i) {
        acc[i] = make_float4(0.f, 0.f, 0.f, 0.f);
        int r = row0 + i;
        ridx[i] = (r < N) ? r : 0;     // clamp for safe loads; store is guarded
    }

    #pragma unroll 1
    for (int k4 = 0; k4 < 25; ++k4) {
        float4 w0 = W4[(k4 * 4 + 0) * 26 + cg];
        float4 w1 = W4[(k4 * 4 + 1) * 26 + cg];
        float4 w2 = W4[(k4 * 4 + 2) * 26 + cg];
        float4 w3 = W4[(k4 * 4 + 3) * 26 + cg];
        #pragma unroll
        for (int i = 0; i < 6; ++i) {
            float4 xv = __ldg(&x4[ridx[i] * C4 + k4]);
            acc[i].x = fmaf(xv.w, w3.x, fmaf(xv.z, w2.x, fmaf(xv.y, w1.x, fmaf(xv.x, w0.x, acc[i].x))));
            acc[i].y = fmaf(xv.w, w3.y, fmaf(xv.z, w2.y, fmaf(xv.y, w1.y, fmaf(xv.x, w0.y, acc[i].y))));
            acc[i].z = fmaf(xv.w, w3.z, fmaf(xv.z, w2.z, fmaf(xv.y, w1.z, fmaf(xv.x, w0.z, acc[i].z))));
            acc[i].w = fmaf(xv.w, w3.w, fmaf(xv.z, w2.w, fmaf(xv.y, w1.w, fmaf(xv.x, w0.w, acc[i].w))));
        }
    }

    float4* y4 = (float4*)g_bufA;
    #pragma unroll
    for (int i = 0; i < 6; ++i) {
        int r = row0 + i;
        if (r < N) y4[r * C4 + cg] = acc[i];
    }
}

// ---------------- fused SpMM + scale + L2-normalize + avg accumulate ----------------
// One warp per row. out[r] = deg_inv[r] * (x[r] + sum_{e in row} x[col[e]]).
// Then avg[r] += out[r] / max(||out[r]||,1e-12) * (1/3). Optionally store out -> g_bufB.
__global__ void __launch_bounds__(256) spmm_fused_k(float* __restrict__ avg, int N, int write_y) {
    int gw = (blockIdx.x * blockDim.x + threadIdx.x) >> 5;
    int lane = threadIdx.x & 31;
    if (gw >= N) return;

    const float4* x4 = (const float4*)g_bufA;
    bool act = lane < C4;

    float4 acc = make_float4(0.f, 0.f, 0.f, 0.f);
    if (act) acc = __ldg(&x4[gw * C4 + lane]);     // self loop

    int beg = g_rowptr[gw];
    int end = g_rowptr[gw + 1];
    for (int base = beg; base < end; base += 32) {
        int idx = base + lane;
        int c = (idx < end) ? __ldg(&g_col[idx]) : 0;
        int m = end - base; if (m > 32) m = 32;
        for (int j = 0; j < m; ++j) {
            int s = __shfl_sync(0xffffffffu, c, j);
            if (act) {
                float4 v = __ldg(&x4[s * C4 + lane]);
                acc.x += v.x; acc.y += v.y; acc.z += v.z; acc.w += v.w;
            }
        }
    }

    float dinv = g_deginv[gw];
    acc.x *= dinv; acc.y *= dinv; acc.z *= dinv; acc.w *= dinv;

    if (write_y && act) ((float4*)g_bufB)[gw * C4 + lane] = acc;

    float p = act ? (acc.x * acc.x + acc.y * acc.y + acc.z * acc.z + acc.w * acc.w) : 0.f;
    #pragma unroll
    for (int o = 16; o; o >>= 1) p += __shfl_xor_sync(0xffffffffu, p, o);

    float s = (1.0f / 3.0f) / fmaxf(sqrtf(p), 1e-12f);
    if (act) {
        float4* a4 = (float4*)avg;
        float4 a = a4[gw * C4 + lane];
        a.x = fmaf(acc.x, s, a.x);
        a.y = fmaf(acc.y, s, a.y);
        a.z = fmaf(acc.z, s, a.z);
        a.w = fmaf(acc.w, s, a.w);
        a4[gw * C4 + lane] = a;
    }
}

// ---------------- launch ----------------

extern "C" void kernel_launch(void* const* d_in, const int* in_sizes, int n_in,
                              void* d_out, int out_size) {
    const float* feat = (const float*)d_in[0];
    const float* W    = (const float*)d_in[1];
    const int*   src  = (const int*)d_in[2];
    const int*   dst  = (const int*)d_in[3];
    float*       avg  = (float*)d_out;

    const int N = in_sizes[0] / DD;   // 50000
    const int E = in_sizes[2];        // 800000
    const int nb = (N + 1023) / 1024; // 49 (<= 64)

    // graph preprocessing (rebuilt every call; deterministic work)
    zero_cnt_k<<<(N + 255) / 256, 256>>>(N);
    count_k<<<(E + 255) / 256, 256>>>(dst, E);
    transW_k<<<(2 * DD * DD + 255) / 256, 256>>>(W);
    scanA_k<<<nb, 1024>>>(N);
    scanB_k<<<1, 64>>>(nb);
    scanC_k<<<(N + 255) / 256, 256>>>(N, E);
    scatter_k<<<(E + 255) / 256, 256>>>(src, dst, E);
    init_avg_k<<<(N * C4 + 255) / 256, 256>>>(feat, avg, N * C4);

    const int gemm_blocks = (N + 59) / 60;
    const int fused_blocks = (N * 32 + 255) / 256;

    // layer 0: bufA = feat @ W0^T ; bufB = SpMM(bufA) ; avg += normalize(bufB)/3
    gemm_k<<<gemm_blocks, 256>>>(feat, 0, N);
    spmm_fused_k<<<fused_blocks, 256>>>(avg, N, 1);

    // layer 1: bufA = bufB @ W1^T ; avg += normalize(SpMM(bufA))/3
    gemm_k<<<gemm_blocks, 256>>>(nullptr, 1, N);
    spmm_fused_k<<<fused_blocks, 256>>>(avg, N, 0);
}

// round 4
// speedup vs baseline: 1.1354x; 1.1354x over previous
#include <cuda_runtime.h>

// Problem constants (fixed by setup_inputs: N=50000, E=800000, D=100, 2 layers)
#define NMAX 50000
#define EMAX 800000
#define DD   100
#define C4   25      // D/4 float4 chunks per row
#define WPITCH 104   // padded pitch (floats) for transposed W rows

typedef unsigned long long u64;

// ---- static device scratch (no runtime allocation allowed) ----
__device__ float g_bufA[NMAX * DD];        // GEMM output / SpMM input
__device__ float g_bufB[NMAX * DD];        // layer-0 SpMM output (x1)
__device__ float g_bufC[NMAX * DD];        // layer-1 SpMM output (x2)
__device__ float g_Wt[2 * DD * WPITCH];    // k-major transposed weights
__device__ int   g_cnt[NMAX];              // per-row edge counts
__device__ int   g_rowptr[NMAX + 1];       // CSR row pointers
__device__ int   g_cursor[NMAX];           // scatter cursors
__device__ float g_deginv[NMAX];           // 1/(cnt+1)  (self loop included)
__device__ int   g_col[EMAX];              // CSR column (src) indices
__device__ float g_sfac[2 * NMAX];         // per-row 1/max(norm,eps) per layer
__device__ int   g_agg[64];                // lookback aggregates
__device__ int   g_flag[64];               // lookback flags

// ---------------- f32x2 helpers ----------------
__device__ __forceinline__ u64 dup2(float a) {
    u64 r; unsigned ai = __float_as_uint(a);
    asm("mov.b64 %0, {%1, %1};" : "=l"(r) : "r"(ai));
    return r;
}
__device__ __forceinline__ void ffma2(u64& acc, u64 a, u64 b) {
    asm("fma.rn.f32x2 %0, %1, %2, %0;" : "+l"(acc) : "l"(a), "l"(b));
}
__device__ __forceinline__ float2 unpk(u64 v) {
    unsigned lo, hi;
    asm("mov.b64 {%0, %1}, %2;" : "=r"(lo), "=r"(hi) : "l"(v));
    return make_float2(__uint_as_float(lo), __uint_as_float(hi));
}

// ---------------- preprocessing ----------------

// zero counts + lookback flags, transpose W (k-major, padded pitch)
__global__ void init_k(const float* __restrict__ W, int N) {
    int i = blockIdx.x * blockDim.x + threadIdx.x;
    if (i < N) g_cnt[i] = 0;
    if (i < 64) { g_flag[i] = 0; g_agg[i] = 0; }
    if (i < 2 * DD * DD) {
        int l = i / (DD * DD);
        int r = i - l * DD * DD;
        int j = r / DD;
        int k = r - j * DD;
        g_Wt[l * DD * WPITCH + k * WPITCH + j] = W[i];
    }
}

__global__ void count_k(const int* __restrict__ dst, int E) {
    int i = blockIdx.x * blockDim.x + threadIdx.x;
    if (i < E) atomicAdd(&g_cnt[__ldg(&dst[i])], 1);
}

// single-kernel exclusive scan with decoupled lookback (49 blocks, all resident)
__global__ void __launch_bounds__(1024) scan_lb_k(int N, int E) {
    __shared__ int wsum[32];
    __shared__ int s_prev;
    int tid = threadIdx.x, bid = blockIdx.x;
    int lane = tid & 31, wid = tid >> 5;
    int i = bid * 1024 + tid;
    int v = (i < N) ? g_cnt[i] : 0;

    // warp inclusive scan
    int x = v;
    #pragma unroll
    for (int o = 1; o < 32; o <<= 1) {
        int t = __shfl_up_sync(0xffffffffu, x, o);
        if (lane >= o) x += t;
    }
    if (lane == 31) wsum[wid] = x;
    __syncthreads();
    if (wid == 0) {
        int s = wsum[lane];
        #pragma unroll
        for (int o = 1; o < 32; o <<= 1) {
            int t = __shfl_up_sync(0xffffffffu, s, o);
            if (lane >= o) s += t;
        }
        wsum[lane] = s;
    }
    __syncthreads();
    int excl = x - v + (wid ? wsum[wid - 1] : 0);
    int total = wsum[31];

    // publish this block's aggregate
    if (tid == 0) {
        g_agg[bid] = total;
        __threadfence();
        atomicExch(&g_flag[bid], 1);
    }
    // lookback: warp 0 sums all predecessor aggregates in parallel
    if (wid == 0) {
        int sum = 0;
        for (int p = lane; p < bid; p += 32) {
            while (atomicAdd(&g_flag[p], 0) == 0) {}
            sum += atomicAdd(&g_agg[p], 0);
        }
        #pragma unroll
        for (int o = 16; o; o >>= 1) sum += __shfl_xor_sync(0xffffffffu, sum, o);
        if (lane == 0) s_prev = sum;
    }
    __syncthreads();
    int base = s_prev;
    if (i < N) {
        int rp = base + excl;
        g_rowptr[i] = rp;
        g_cursor[i] = rp;
        g_deginv[i] = 1.0f / (float)(v + 1);   // +1 self loop
    }
    if (i == 0) g_rowptr[N] = E;
}

__global__ void scatter_k(const int* __restrict__ src, const int* __restrict__ dst, int E) {
    int i = blockIdx.x * blockDim.x + threadIdx.x;
    if (i < E) {
        int d = __ldg(&dst[i]);
        int pos = atomicAdd(&g_cursor[d], 1);
        g_col[pos] = __ldg(&src[i]);
    }
}

// ---------------- GEMM: g_bufA = x @ W[layer]^T  (packed f32x2) ----------------
// 60 rows per CTA; 250 active threads: cg = tid%25 (4 output cols), rg = tid/25
// (6 rows each). W tile (k-major) in SMEM: cg lanes read contiguous 16B ->
// conflict-free; each float4 yields two naturally-packed f32x2 column pairs.
__global__ void __launch_bounds__(256) gemm_k(const float* __restrict__ xin, int layer, int N) {
    __shared__ float Ws[DD * WPITCH];   // 41.6 KB
    const float* wt = g_Wt + layer * DD * WPITCH;
    for (int i = threadIdx.x; i < DD * WPITCH; i += 256) Ws[i] = wt[i];
    __syncthreads();

    int tid = threadIdx.x;
    if (tid >= 250) return;
    int cg = tid % 25;
    int rg = tid / 25;                 // 0..9
    int row0 = blockIdx.x * 60 + rg * 6;

    const float4* x4 = (const float4*)(xin ? xin : g_bufB);
    const double2* Wd = (const double2*)Ws;   // pitch: 26 double2 per k-row

    u64 a01[6], a23[6];
    int ridx[6];
    #pragma unroll
    for (int i = 0; i < 6; ++i) {
        a01[i] = 0ull; a23[i] = 0ull;
        int r = row0 + i;
        ridx[i] = (r < N) ? r : 0;     // clamp for safe loads; store is guarded
    }

    #pragma unroll 1
    for (int k4 = 0; k4 < 25; ++k4) {
        u64 w01[4], w23[4];
        #pragma unroll
        for (int kk = 0; kk < 4; ++kk) {
            double2 t = Wd[(k4 * 4 + kk) * 26 + cg];
            w01[kk] = __double_as_longlong(t.x);
            w23[kk] = __double_as_longlong(t.y);
        }
        #pragma unroll
        for (int i = 0; i < 6; ++i) {
            float4 xv = __ldg(&x4[ridx[i] * C4 + k4]);
            u64 d0 = dup2(xv.x), d1 = dup2(xv.y), d2 = dup2(xv.z), d3 = dup2(xv.w);
            ffma2(a01[i], d0, w01[0]); ffma2(a23[i], d0, w23[0]);
            ffma2(a01[i], d1, w01[1]); ffma2(a23[i], d1, w23[1]);
            ffma2(a01[i], d2, w01[2]); ffma2(a23[i], d2, w23[2]);
            ffma2(a01[i], d3, w01[3]); ffma2(a23[i], d3, w23[3]);
        }
    }

    float4* y4 = (float4*)g_bufA;
    #pragma unroll
    for (int i = 0; i < 6; ++i) {
        int r = row0 + i;
        if (r < N) {
            float2 lo = unpk(a01[i]);
            float2 hi = unpk(a23[i]);
            y4[r * C4 + cg] = make_float4(lo.x, lo.y, hi.x, hi.y);
        }
    }
}

// ---------------- SpMM: out[r] = deg_inv[r]*(x[r] + sum_e x[col[e]]) ----------------
// One warp per row; stores per-row normalize scale into g_sfac[layer].
__global__ void __launch_bounds__(256) spmm_k(float* __restrict__ out, int layer, int N) {
    int gw = (blockIdx.x * blockDim.x + threadIdx.x) >> 5;
    int lane = threadIdx.x & 31;
    if (gw >= N) return;

    const float4* x4 = (const float4*)g_bufA;
    bool act = lane < C4;

    float4 acc = make_float4(0.f, 0.f, 0.f, 0.f);
    if (act) acc = __ldg(&x4[gw * C4 + lane]);     // self loop

    int beg = g_rowptr[gw];
    int end = g_rowptr[gw + 1];
    for (int base = beg; base < end; base += 32) {
        int idx = base + lane;
        int c = (idx < end) ? __ldg(&g_col[idx]) : 0;
        int m = end - base; if (m > 32) m = 32;
        int j = 0;
        for (; j + 1 < m; j += 2) {
            int s0 = __shfl_sync(0xffffffffu, c, j);
            int s1 = __shfl_sync(0xffffffffu, c, j + 1);
            if (act) {
                float4 v0 = __ldg(&x4[s0 * C4 + lane]);
                float4 v1 = __ldg(&x4[s1 * C4 + lane]);
                acc.x += v0.x; acc.y += v0.y; acc.z += v0.z; acc.w += v0.w;
                acc.x += v1.x; acc.y += v1.y; acc.z += v1.z; acc.w += v1.w;
            }
        }
        if (j < m) {
            int s0 = __shfl_sync(0xffffffffu, c, j);
            if (act) {
                float4 v0 = __ldg(&x4[s0 * C4 + lane]);
                acc.x += v0.x; acc.y += v0.y; acc.z += v0.z; acc.w += v0.w;
            }
        }
    }

    float dinv = g_deginv[gw];
    acc.x *= dinv; acc.y *= dinv; acc.z *= dinv; acc.w *= dinv;

    if (act) ((float4*)out)[gw * C4 + lane] = acc;

    float p = act ? (acc.x * acc.x + acc.y * acc.y + acc.z * acc.z + acc.w * acc.w) : 0.f;
    #pragma unroll
    for (int o = 16; o; o >>= 1) p += __shfl_xor_sync(0xffffffffu, p, o);

    if (lane == 0) g_sfac[layer * NMAX + gw] = 1.0f / fmaxf(sqrtf(p), 1e-12f);
}

// ---------------- finale: avg = (feat + s1*x1 + s2*x2) / 3 ----------------
__global__ void finale_k(const float* __restrict__ feat, float* __restrict__ avg, int N) {
    int i = blockIdx.x * blockDim.x + threadIdx.x;
    if (i >= N * C4) return;
    int row = i / C4;
    float s1 = __ldg(&g_sfac[row]);
    float s2 = __ldg(&g_sfac[NMAX + row]);
    float4 f  = ((const float4*)feat)[i];
    float4 x1 = ((const float4*)g_bufB)[i];
    float4 x2 = ((const float4*)g_bufC)[i];
    const float c = 1.0f / 3.0f;
    float4 o;
    o.x = (f.x + s1 * x1.x + s2 * x2.x) * c;
    o.y = (f.y + s1 * x1.y + s2 * x2.y) * c;
    o.z = (f.z + s1 * x1.z + s2 * x2.z) * c;
    o.w = (f.w + s1 * x1.w + s2 * x2.w) * c;
    ((float4*)avg)[i] = o;
}

// ---------------- launch ----------------

extern "C" void kernel_launch(void* const* d_in, const int* in_sizes, int n_in,
                              void* d_out, int out_size) {
    const float* feat = (const float*)d_in[0];
    const float* W    = (const float*)d_in[1];
    const int*   src  = (const int*)d_in[2];
    const int*   dst  = (const int*)d_in[3];
    float*       avg  = (float*)d_out;

    const int N = in_sizes[0] / DD;   // 50000
    const int E = in_sizes[2];        // 800000
    const int nb = (N + 1023) / 1024; // 49 (<= 64, all resident)

    // resolve device-symbol addresses (no allocation; capture-safe)
    void* pB; cudaGetSymbolAddress(&pB, g_bufB);
    void* pC; cudaGetSymbolAddress(&pC, g_bufC);

    init_k<<<(N + 255) / 256, 256>>>(W, N);
    count_k<<<(E + 255) / 256, 256>>>(dst, E);
    scan_lb_k<<<nb, 1024>>>(N, E);
    scatter_k<<<(E + 255) / 256, 256>>>(src, dst, E);

    const int gemm_blocks = (N + 59) / 60;
    const int spmm_blocks = (N * 32 + 255) / 256;

    gemm_k<<<gemm_blocks, 256>>>(feat, 0, N);        // bufA = feat @ W0^T
    spmm_k<<<spmm_blocks, 256>>>((float*)pB, 0, N);  // bufB = x1, sfac[0]
    gemm_k<<<gemm_blocks, 256>>>(nullptr, 1, N);     // bufA = bufB @ W1^T
    spmm_k<<<spmm_blocks, 256>>>((float*)pC, 1, N);  // bufC = x2, sfac[1]
    finale_k<<<(N * C4 + 255) / 256, 256>>>(feat, avg, N);
}

// round 7
// speedup vs baseline: 1.1864x; 1.0449x over previous
#include <cuda_runtime.h>

// Problem constants (fixed by setup_inputs: N=50000, E=800000, D=100, 2 layers)
#define NMAX 50000
#define EMAX 800000
#define DD   100
#define C4   25      // D/4 float4 chunks per dense row (feat / output)
#define CP   32      // pitched float4 chunks per internal row (512B, line-aligned)
#define WPITCH 104   // padded pitch (floats) for transposed W rows

typedef unsigned long long u64;

// ---- static device scratch (no runtime allocation allowed) ----
__device__ float g_bufA[NMAX * CP * 4];    // GEMM output / SpMM input (pitched)
__device__ float g_bufB[NMAX * CP * 4];    // layer-0 SpMM output x1 (pitched)
__device__ float g_bufC[NMAX * CP * 4];    // layer-1 SpMM output x2 (pitched)
__device__ float g_Wt[2 * DD * WPITCH];    // k-major transposed weights
__device__ int   g_cnt[NMAX];              // per-row edge counts
__device__ int   g_rowptr[NMAX + 1];       // CSR row pointers
__device__ float g_deginv[NMAX];           // 1/(cnt+1)  (self loop included)
__device__ int   g_col[EMAX];              // CSR column (src) indices
__device__ int   g_rank[EMAX];             // per-edge rank within its dst row
__device__ float g_sfac[2 * NMAX];         // per-row 1/max(norm,eps) per layer
__device__ int   g_agg[64];                // lookback aggregates
__device__ int   g_flag[64];               // lookback flags

// ---------------- f32x2 helpers ----------------
__device__ __forceinline__ u64 dup2(float a) {
    u64 r; unsigned ai = __float_as_uint(a);
    asm("mov.b64 %0, {%1, %1};" : "=l"(r) : "r"(ai));
    return r;
}
__device__ __forceinline__ void ffma2(u64& acc, u64 a, u64 b) {
    asm("fma.rn.f32x2 %0, %1, %2, %0;" : "+l"(acc) : "l"(a), "l"(b));
}
__device__ __forceinline__ float2 unpk(u64 v) {
    unsigned lo, hi;
    asm("mov.b64 {%0, %1}, %2;" : "=r"(lo), "=r"(hi) : "l"(v));
    return make_float2(__uint_as_float(lo), __uint_as_float(hi));
}

// ---------------- preprocessing ----------------

// zero counts + lookback flags, transpose W (k-major, padded pitch)
__global__ void init_k(const float* __restrict__ W, int N) {
    int i = blockIdx.x * blockDim.x + threadIdx.x;
    if (i < N) g_cnt[i] = 0;
    if (i < 64) { g_flag[i] = 0; g_agg[i] = 0; }
    if (i < 2 * DD * DD) {
        int l = i / (DD * DD);
        int r = i - l * DD * DD;
        int j = r / DD;
        int k = r - j * DD;
        g_Wt[l * DD * WPITCH + k * WPITCH + j] = W[i];
    }
}

// histogram; the atomic's return value is the edge's rank within its row
__global__ void count_k(const int* __restrict__ dst, int E) {
    int i = blockIdx.x * blockDim.x + threadIdx.x;
    if (i < E) g_rank[i] = atomicAdd(&g_cnt[__ldg(&dst[i])], 1);
}

// single-kernel exclusive scan with decoupled lookback (49 blocks, all resident)
__global__ void __launch_bounds__(1024) scan_lb_k(int N, int E) {
    __shared__ int wsum[32];
    __shared__ int s_prev;
    int tid = threadIdx.x, bid = blockIdx.x;
    int lane = tid & 31, wid = tid >> 5;
    int i = bid * 1024 + tid;
    int v = (i < N) ? g_cnt[i] : 0;

    int x = v;
    #pragma unroll
    for (int o = 1; o < 32; o <<= 1) {
        int t = __shfl_up_sync(0xffffffffu, x, o);
        if (lane >= o) x += t;
    }
    if (lane == 31) wsum[wid] = x;
    __syncthreads();
    if (wid == 0) {
        int s = wsum[lane];
        #pragma unroll
        for (int o = 1; o < 32; o <<= 1) {
            int t = __shfl_up_sync(0xffffffffu, s, o);
            if (lane >= o) s += t;
        }
        wsum[lane] = s;
    }
    __syncthreads();
    int excl = x - v + (wid ? wsum[wid - 1] : 0);
    int total = wsum[31];

    if (tid == 0) {
        g_agg[bid] = total;
        __threadfence();
        atomicExch(&g_flag[bid], 1);
    }
    if (wid == 0) {
        int sum = 0;
        for (int p = lane; p < bid; p += 32) {
            while (atomicAdd(&g_flag[p], 0) == 0) {}
            sum += atomicAdd(&g_agg[p], 0);
        }
        #pragma unroll
        for (int o = 16; o; o >>= 1) sum += __shfl_xor_sync(0xffffffffu, sum, o);
        if (lane == 0) s_prev = sum;
    }
    __syncthreads();
    int base = s_prev;
    if (i < N) {
        g_rowptr[i] = base + excl;
        g_deginv[i] = 1.0f / (float)(v + 1);   // +1 self loop
    }
    if (i == 0) g_rowptr[N] = E;
}

// atomic-free CSR scatter: pos = rowptr[dst] + rank
__global__ void scatter_k(const int* __restrict__ src, const int* __restrict__ dst, int E) {
    int i = blockIdx.x * blockDim.x + threadIdx.x;
    if (i < E) {
        int d = __ldg(&dst[i]);
        int pos = __ldg(&g_rowptr[d]) + g_rank[i];
        g_col[pos] = __ldg(&src[i]);
    }
}

// ---------------- GEMM: g_bufA = x @ W[layer]^T  (packed f32x2) ----------------
// 60 rows per CTA; 250 active threads: cg = tid%25 (4 output cols), rg = tid/25
// (6 rows each). W tile (k-major) in SMEM: cg lanes read contiguous 16B ->
// conflict-free; each float4 yields two naturally-packed f32x2 column pairs.
__global__ void __launch_bounds__(256) gemm_k(const float* __restrict__ xin, int xs4,
                                              int layer, int N) {
    __shared__ float Ws[DD * WPITCH];   // 41.6 KB
    const float* wt = g_Wt + layer * DD * WPITCH;
    for (int i = threadIdx.x; i < DD * WPITCH; i += 256) Ws[i] = wt[i];
    __syncthreads();

    int tid = threadIdx.x;
    if (tid >= 250) return;
    int cg = tid % 25;
    int rg = tid / 25;                 // 0..9
    int row0 = blockIdx.x * 60 + rg * 6;

    const float4* x4 = (const float4*)xin;
    const double2* Wd = (const double2*)Ws;   // pitch: 26 double2 per k-row

    u64 a01[6], a23[6];
    int ridx[6];
    #pragma unroll
    for (int i = 0; i < 6; ++i) {
        a01[i] = 0ull; a23[i] = 0ull;
        int r = row0 + i;
        ridx[i] = (r < N) ? r : 0;     // clamp for safe loads; store is guarded
    }

    #pragma unroll 1
    for (int k4 = 0; k4 < 25; ++k4) {
        u64 w01[4], w23[4];
        #pragma unroll
        for (int kk = 0; kk < 4; ++kk) {
            double2 t = Wd[(k4 * 4 + kk) * 26 + cg];
            w01[kk] = __double_as_longlong(t.x);
            w23[kk] = __double_as_longlong(t.y);
        }
        #pragma unroll
        for (int i = 0; i < 6; ++i) {
            float4 xv = __ldg(&x4[ridx[i] * xs4 + k4]);
            u64 d0 = dup2(xv.x), d1 = dup2(xv.y), d2 = dup2(xv.z), d3 = dup2(xv.w);
            ffma2(a01[i], d0, w01[0]); ffma2(a23[i], d0, w23[0]);
            ffma2(a01[i], d1, w01[1]); ffma2(a23[i], d1, w23[1]);
            ffma2(a01[i], d2, w01[2]); ffma2(a23[i], d2, w23[2]);
            ffma2(a01[i], d3, w01[3]); ffma2(a23[i], d3, w23[3]);
        }
    }

    float4* y4 = (float4*)g_bufA;   // pitched CP float4 per row
    #pragma unroll
    for (int i = 0; i < 6; ++i) {
        int r = row0 + i;
        if (r < N) {
            float2 lo = unpk(a01[i]);
            float2 hi = unpk(a23[i]);
            y4[r * CP + cg] = make_float4(lo.x, lo.y, hi.x, hi.y);
        }
    }
}

// ---------------- SpMM: out[r] = deg_inv[r]*(x[r] + sum_e x[col[e]]) ----------------
// One warp per row (pitched, line-aligned rows); stores per-row normalize scale.
__global__ void __launch_bounds__(256) spmm_k(float* __restrict__ out, int layer, int N) {
    int gw = (blockIdx.x * blockDim.x + threadIdx.x) >> 5;
    int lane = threadIdx.x & 31;
    if (gw >= N) return;

    const float4* x4 = (const float4*)g_bufA;
    bool act = lane < C4;

    float4 acc = make_float4(0.f, 0.f, 0.f, 0.f);
    if (act) acc = __ldg(&x4[gw * CP + lane]);     // self loop

    int beg = g_rowptr[gw];
    int end = g_rowptr[gw + 1];
    for (int base = beg; base < end; base += 32) {
        int idx = base + lane;
        int c = (idx < end) ? __ldg(&g_col[idx]) : 0;
        int m = end - base; if (m > 32) m = 32;
        int j = 0;
        for (; j + 1 < m; j += 2) {
            int s0 = __shfl_sync(0xffffffffu, c, j);
            int s1 = __shfl_sync(0xffffffffu, c, j + 1);
            if (act) {
                float4 v0 = __ldg(&x4[s0 * CP + lane]);
                float4 v1 = __ldg(&x4[s1 * CP + lane]);
                acc.x += v0.x; acc.y += v0.y; acc.z += v0.z; acc.w += v0.w;
                acc.x += v1.x; acc.y += v1.y; acc.z += v1.z; acc.w += v1.w;
            }
        }
        if (j < m) {
            int s0 = __shfl_sync(0xffffffffu, c, j);
            if (act) {
                float4 v0 = __ldg(&x4[s0 * CP + lane]);
                acc.x += v0.x; acc.y += v0.y; acc.z += v0.z; acc.w += v0.w;
            }
        }
    }

    float dinv = g_deginv[gw];
    acc.x *= dinv; acc.y *= dinv; acc.z *= dinv; acc.w *= dinv;

    if (act) ((float4*)out)[gw * CP + lane] = acc;

    float p = act ? (acc.x * acc.x + acc.y * acc.y + acc.z * acc.z + acc.w * acc.w) : 0.f;
    #pragma unroll
    for (int o = 16; o; o >>= 1) p += __shfl_xor_sync(0xffffffffu, p, o);

    if (lane == 0) g_sfac[layer * NMAX + gw] = 1.0f / fmaxf(sqrtf(p), 1e-12f);
}

// ---------------- finale: avg = (feat + s1*x1 + s2*x2) / 3 ----------------
__global__ void finale_k(const float* __restrict__ feat, float* __restrict__ avg, int N) {
    int i = blockIdx.x * blockDim.x + threadIdx.x;
    if (i >= N * C4) return;
    int row = i / C4;
    int c   = i - row * C4;
    float s1 = __ldg(&g_sfac[row]);
    float s2 = __ldg(&g_sfac[NMAX + row]);
    float4 f  = ((const float4*)feat)[i];
    float4 x1 = ((const float4*)g_bufB)[row * CP + c];
    float4 x2 = ((const float4*)g_bufC)[row * CP + c];
    const float k = 1.0f / 3.0f;
    float4 o;
    o.x = (f.x + s1 * x1.x + s2 * x2.x) * k;
    o.y = (f.y + s1 * x1.y + s2 * x2.y) * k;
    o.z = (f.z + s1 * x1.z + s2 * x2.z) * k;
    o.w = (f.w + s1 * x1.w + s2 * x2.w) * k;
    ((float4*)avg)[i] = o;
}

// ---------------- launch ----------------

extern "C" void kernel_launch(void* const* d_in, const int* in_sizes, int n_in,
                              void* d_out, int out_size) {
    const float* feat = (const float*)d_in[0];
    const float* W    = (const float*)d_in[1];
    const int*   src  = (const int*)d_in[2];
    const int*   dst  = (const int*)d_in[3];
    float*       avg  = (float*)d_out;

    const int N = in_sizes[0] / DD;   // 50000
    const int E = in_sizes[2];        // 800000
    const int nb = (N + 1023) / 1024; // 49 (<= 64, all resident)

    // lazily create side stream + events once (first call runs outside capture)
    static cudaStream_t s2 = nullptr;
    static cudaEvent_t evFork = nullptr, evJoin = nullptr;
    if (!s2) {
        cudaStreamCreateWithFlags(&s2, cudaStreamNonBlocking);
        cudaEventCreateWithFlags(&evFork, cudaEventDisableTiming);
        cudaEventCreateWithFlags(&evJoin, cudaEventDisableTiming);
    }

    void* pB; cudaGetSymbolAddress(&pB, g_bufB);
    void* pC; cudaGetSymbolAddress(&pC, g_bufC);

    const int gemm_blocks = (N + 59) / 60;
    const int spmm_blocks = (N * 32 + 255) / 256;

    // main chain: graph preprocessing
    init_k<<<(N + 255) / 256, 256>>>(W, N);

    // fork: layer-0 GEMM depends only on feat + g_Wt (from init_k)
    cudaEventRecord(evFork, 0);
    cudaStreamWaitEvent(s2, evFork, 0);
    gemm_k<<<gemm_blocks, 256, 0, s2>>>(feat, C4, 0, N);   // bufA = feat @ W0^T
    cudaEventRecord(evJoin, s2);

    count_k<<<(E + 255) / 256, 256>>>(dst, E);
    scan_lb_k<<<nb, 1024>>>(N, E);
    scatter_k<<<(E + 255) / 256, 256>>>(src, dst, E);

    // join: SpMM needs both CSR (main) and bufA (s2)
    cudaStreamWaitEvent(0, evJoin, 0);
    spmm_k<<<spmm_blocks, 256>>>((float*)pB, 0, N);        // bufB = x1, sfac[0]
    gemm_k<<<gemm_blocks, 256>>>((const float*)pB, CP, 1, N); // bufA = bufB @ W1^T
    spmm_k<<<spmm_blocks, 256>>>((float*)pC, 1, N);        // bufC = x2, sfac[1]
    finale_k<<<(N * C4 + 255) / 256, 256>>>(feat, avg, N);
}